// round 1
// baseline (speedup 1.0000x reference)
#include <cuda_runtime.h>

// ============================================================================
// Fused scaled-dot-product attention (fp32), B=2 H=16 S=2048 D=64.
// Outputs: d_out[0 : B*H*S*D)          = context
//          d_out[B*H*S*D : +B*H*S*S)   = attention (post-softmax)
//
// One block = one (b*h, 16-query-row) tile. All of QK^T, +mask, softmax,
// attention store, and P@V happen with the 16x2048 score tile resident in
// shared memory (no gmem round-trip for P). Inner products use packed
// fma.rn.f32x2 (2 fp32 FMA per instruction on sm_103a).
// ============================================================================

namespace {

constexpr int Bc  = 2;
constexpr int Hc  = 16;
constexpr int Sc  = 2048;
constexpr int Dc  = 64;
constexpr int TQ  = 16;    // query rows per block
constexpr int KTW = 256;   // K-tile width (score columns per supertile)
constexpr int KP  = 65;    // K smem pitch (odd -> conflict-free column reads)
constexpr int SP  = 2052;  // score row pitch (= 4 mod 8 -> q-row bank stagger)
constexpr int NT  = 256;   // threads per block

constexpr int SM_QT     = 0;                  // Qt[d][q]  : 64*16
constexpr int SM_SC     = SM_QT + Dc * TQ;    // SC[q][SP] : 16*2052
constexpr int SM_KV     = SM_SC + TQ * SP;    // KV        : 256*65 (K) / V / partials
constexpr int SM_FLOATS = SM_KV + KTW * KP;   // = 50496 floats = 201984 bytes

__device__ __forceinline__ unsigned long long pk2(float x, float y) {
    unsigned long long r;
    asm("mov.b64 %0, {%1, %2};"
        : "=l"(r) : "r"(__float_as_uint(x)), "r"(__float_as_uint(y)));
    return r;
}

__device__ __forceinline__ void upk2(unsigned long long v, float& x, float& y) {
    unsigned int a, b;
    asm("mov.b64 {%0, %1}, %2;" : "=r"(a), "=r"(b) : "l"(v));
    x = __uint_as_float(a);
    y = __uint_as_float(b);
}

__device__ __forceinline__ unsigned long long
fma2(unsigned long long a, unsigned long long b, unsigned long long c) {
    unsigned long long d;
    asm("fma.rn.f32x2 %0, %1, %2, %3;" : "=l"(d) : "l"(a), "l"(b), "l"(c));
    return d;
}

} // namespace

__global__ void __launch_bounds__(NT, 1)
attn_fused_kernel(const float* __restrict__ Q, const float* __restrict__ K,
                  const float* __restrict__ V, const float* __restrict__ M,
                  float* __restrict__ OC, float* __restrict__ OA)
{
    extern __shared__ float sm[];
    float* Qt = sm + SM_QT;
    float* SC = sm + SM_SC;
    float* KV = sm + SM_KV;

    const int t  = threadIdx.x;
    const int qt = blockIdx.x;   // query tile (0..127)
    const int bh = blockIdx.y;   // b*H + h    (0..31)

    const float* Qb = Q + ((long)bh * Sc + qt * TQ) * Dc;
    const float* Kb = K + (long)bh * Sc * Dc;
    const float* Vb = V + (long)bh * Sc * Dc;
    const float* Mb = M + ((long)bh * Sc + (long)qt * TQ) * Sc;
    float*       Ab = OA + ((long)bh * Sc + (long)qt * TQ) * Sc;
    float*       Cb = OC + ((long)bh * Sc + qt * TQ) * Dc;

    // ---------------- Phase 0: stage Q transposed (Qt[d][q]) ----------------
    {
        const int q  = t >> 4;          // 0..15
        const int d0 = (t & 15) << 2;   // 0,4,...,60
        float4 v = *reinterpret_cast<const float4*>(Qb + q * Dc + d0);
        Qt[(d0 + 0) * TQ + q] = v.x;
        Qt[(d0 + 1) * TQ + q] = v.y;
        Qt[(d0 + 2) * TQ + q] = v.z;
        Qt[(d0 + 3) * TQ + q] = v.w;
    }

    const int a = t >> 6;   // q group: rows 4a..4a+3
    const int g = t & 63;   // k lane : columns g, g+64, g+128, g+192

    // ---------------- Phase 1: S = (Q K^T) * 1/sqrt(D) ----------------------
    for (int st = 0; st < Sc / KTW; ++st) {
        __syncthreads();
        // Load K supertile rows [st*256, +256) into KV[k][KP], coalesced LDG.
        {
            const float* src = Kb + (long)st * KTW * Dc;
            #pragma unroll
            for (int ii = 0; ii < (KTW * Dc) / (NT * 4); ++ii) {  // 16 iters
                const int idx4 = t + NT * ii;
                const int kr = idx4 >> 4;
                const int d0 = (idx4 & 15) << 2;
                float4 v = *reinterpret_cast<const float4*>(src + (size_t)idx4 * 4);
                float* dst = KV + kr * KP + d0;
                dst[0] = v.x; dst[1] = v.y; dst[2] = v.z; dst[3] = v.w;
            }
        }
        __syncthreads();

        unsigned long long a00 = 0ull, a01 = 0ull, a10 = 0ull, a11 = 0ull,
                           a20 = 0ull, a21 = 0ull, a30 = 0ull, a31 = 0ull;
        #pragma unroll 8
        for (int d = 0; d < Dc; ++d) {
            const float4 qv = *reinterpret_cast<const float4*>(Qt + d * TQ + 4 * a);
            const float k0 = KV[(g      ) * KP + d];
            const float k1 = KV[(g +  64) * KP + d];
            const float k2 = KV[(g + 128) * KP + d];
            const float k3 = KV[(g + 192) * KP + d];
            const unsigned long long k01 = pk2(k0, k1);
            const unsigned long long k23 = pk2(k2, k3);
            const unsigned long long qx = pk2(qv.x, qv.x);
            const unsigned long long qy = pk2(qv.y, qv.y);
            const unsigned long long qz = pk2(qv.z, qv.z);
            const unsigned long long qw = pk2(qv.w, qv.w);
            a00 = fma2(qx, k01, a00);  a01 = fma2(qx, k23, a01);
            a10 = fma2(qy, k01, a10);  a11 = fma2(qy, k23, a11);
            a20 = fma2(qz, k01, a20);  a21 = fma2(qz, k23, a21);
            a30 = fma2(qw, k01, a30);  a31 = fma2(qw, k23, a31);
        }

        const float scl = 0.125f;  // 1/sqrt(64)
        {
            float s0, s1, s2, s3;
            float* row;
            row = SC + (4 * a + 0) * SP + st * KTW;
            upk2(a00, s0, s1); upk2(a01, s2, s3);
            row[g] = s0 * scl; row[g + 64] = s1 * scl;
            row[g + 128] = s2 * scl; row[g + 192] = s3 * scl;

            row = SC + (4 * a + 1) * SP + st * KTW;
            upk2(a10, s0, s1); upk2(a11, s2, s3);
            row[g] = s0 * scl; row[g + 64] = s1 * scl;
            row[g + 128] = s2 * scl; row[g + 192] = s3 * scl;

            row = SC + (4 * a + 2) * SP + st * KTW;
            upk2(a20, s0, s1); upk2(a21, s2, s3);
            row[g] = s0 * scl; row[g + 64] = s1 * scl;
            row[g + 128] = s2 * scl; row[g + 192] = s3 * scl;

            row = SC + (4 * a + 3) * SP + st * KTW;
            upk2(a30, s0, s1); upk2(a31, s2, s3);
            row[g] = s0 * scl; row[g + 64] = s1 * scl;
            row[g + 128] = s2 * scl; row[g + 192] = s3 * scl;
        }
    }
    __syncthreads();

    // ---------------- Softmax (+mask), store attention ----------------------
    {
        const int w = t >> 5, lane = t & 31;
        #pragma unroll
        for (int rr = 0; rr < 2; ++rr) {
            const int r = w * 2 + rr;           // 8 warps x 2 rows = 16 rows
            float* row = SC + r * SP;
            const float* mrow = Mb + (long)r * Sc;

            float mx = -3.0e38f;
            #pragma unroll
            for (int i = 0; i < Sc / 128; ++i) {  // 16 iters of float4
                const int c = (lane + i * 32) << 2;
                float4 s = *reinterpret_cast<float4*>(row + c);
                const float4 m = *reinterpret_cast<const float4*>(mrow + c);
                s.x += m.x; s.y += m.y; s.z += m.z; s.w += m.w;
                *reinterpret_cast<float4*>(row + c) = s;
                mx = fmaxf(mx, fmaxf(fmaxf(s.x, s.y), fmaxf(s.z, s.w)));
            }
            #pragma unroll
            for (int o = 16; o > 0; o >>= 1)
                mx = fmaxf(mx, __shfl_xor_sync(0xffffffffu, mx, o));

            float sum = 0.f;
            #pragma unroll
            for (int i = 0; i < Sc / 128; ++i) {
                const int c = (lane + i * 32) << 2;
                float4 s = *reinterpret_cast<float4*>(row + c);
                s.x = __expf(s.x - mx); s.y = __expf(s.y - mx);
                s.z = __expf(s.z - mx); s.w = __expf(s.w - mx);
                *reinterpret_cast<float4*>(row + c) = s;
                sum += (s.x + s.y) + (s.z + s.w);
            }
            #pragma unroll
            for (int o = 16; o > 0; o >>= 1)
                sum += __shfl_xor_sync(0xffffffffu, sum, o);
            const float inv = 1.0f / sum;

            float* arow = Ab + (long)r * Sc;
            #pragma unroll
            for (int i = 0; i < Sc / 128; ++i) {
                const int c = (lane + i * 32) << 2;
                float4 s = *reinterpret_cast<float4*>(row + c);
                s.x *= inv; s.y *= inv; s.z *= inv; s.w *= inv;
                *reinterpret_cast<float4*>(row + c) = s;          // keep for P@V
                *reinterpret_cast<float4*>(arow + c) = s;          // attention out
            }
        }
    }

    // ---------------- Phase 2: C = P @ V ------------------------------------
    const int p  = t >> 6;         // k partition (0..3)
    const int q4 = (t >> 4) & 3;   // q rows 4*q4..4*q4+3
    const int dg = t & 15;         // d cols 4*dg..4*dg+3
    unsigned long long c00 = 0ull, c01 = 0ull, c10 = 0ull, c11 = 0ull,
                       c20 = 0ull, c21 = 0ull, c30 = 0ull, c31 = 0ull;

    for (int vt = 0; vt < Sc / 128; ++vt) {   // 16 V tiles of 128 rows
        __syncthreads();
        {
            const float4* src =
                reinterpret_cast<const float4*>(Vb + (long)vt * 128 * Dc);
            float4* dst = reinterpret_cast<float4*>(KV);
            #pragma unroll
            for (int ii = 0; ii < (128 * Dc) / (NT * 4); ++ii)  // 8 iters
                dst[t + NT * ii] = src[t + NT * ii];
        }
        __syncthreads();

        #pragma unroll 4
        for (int kk = 0; kk < 32; kk += 2) {
            const int k = p * 32 + kk;
            const float4 v0 = *reinterpret_cast<const float4*>(KV + (k    ) * Dc + 4 * dg);
            const float4 v1 = *reinterpret_cast<const float4*>(KV + (k + 1) * Dc + 4 * dg);
            const unsigned long long v0a = pk2(v0.x, v0.y), v0b = pk2(v0.z, v0.w);
            const unsigned long long v1a = pk2(v1.x, v1.y), v1b = pk2(v1.z, v1.w);
            const int kg = vt * 128 + k;
            const float* pc = SC + kg;

            float2 pv; unsigned long long pa, pb;
            pv = *reinterpret_cast<const float2*>(pc + (4 * q4 + 0) * SP);
            pa = pk2(pv.x, pv.x); pb = pk2(pv.y, pv.y);
            c00 = fma2(pa, v0a, c00); c01 = fma2(pa, v0b, c01);
            c00 = fma2(pb, v1a, c00); c01 = fma2(pb, v1b, c01);

            pv = *reinterpret_cast<const float2*>(pc + (4 * q4 + 1) * SP);
            pa = pk2(pv.x, pv.x); pb = pk2(pv.y, pv.y);
            c10 = fma2(pa, v0a, c10); c11 = fma2(pa, v0b, c11);
            c10 = fma2(pb, v1a, c10); c11 = fma2(pb, v1b, c11);

            pv = *reinterpret_cast<const float2*>(pc + (4 * q4 + 2) * SP);
            pa = pk2(pv.x, pv.x); pb = pk2(pv.y, pv.y);
            c20 = fma2(pa, v0a, c20); c21 = fma2(pa, v0b, c21);
            c20 = fma2(pb, v1a, c20); c21 = fma2(pb, v1b, c21);

            pv = *reinterpret_cast<const float2*>(pc + (4 * q4 + 3) * SP);
            pa = pk2(pv.x, pv.x); pb = pk2(pv.y, pv.y);
            c30 = fma2(pa, v0a, c30); c31 = fma2(pa, v0b, c31);
            c30 = fma2(pb, v1a, c30); c31 = fma2(pb, v1b, c31);
        }
    }

    // Cross-partition reduction through smem, then store context.
    __syncthreads();
    {
        float s0, s1, s2, s3;
        float* dst;
        dst = KV + p * 1024 + (4 * q4 + 0) * Dc + 4 * dg;
        upk2(c00, s0, s1); upk2(c01, s2, s3);
        *reinterpret_cast<float4*>(dst) = make_float4(s0, s1, s2, s3);
        dst = KV + p * 1024 + (4 * q4 + 1) * Dc + 4 * dg;
        upk2(c10, s0, s1); upk2(c11, s2, s3);
        *reinterpret_cast<float4*>(dst) = make_float4(s0, s1, s2, s3);
        dst = KV + p * 1024 + (4 * q4 + 2) * Dc + 4 * dg;
        upk2(c20, s0, s1); upk2(c21, s2, s3);
        *reinterpret_cast<float4*>(dst) = make_float4(s0, s1, s2, s3);
        dst = KV + p * 1024 + (4 * q4 + 3) * Dc + 4 * dg;
        upk2(c30, s0, s1); upk2(c31, s2, s3);
        *reinterpret_cast<float4*>(dst) = make_float4(s0, s1, s2, s3);
    }
    __syncthreads();
    {
        const float4* kv4 = reinterpret_cast<const float4*>(KV);
        const float4 r0 = kv4[t];
        const float4 r1 = kv4[t + 256];
        const float4 r2 = kv4[t + 512];
        const float4 r3 = kv4[t + 768];
        float4 o;
        o.x = (r0.x + r1.x) + (r2.x + r3.x);
        o.y = (r0.y + r1.y) + (r2.y + r3.y);
        o.z = (r0.z + r1.z) + (r2.z + r3.z);
        o.w = (r0.w + r1.w) + (r2.w + r3.w);
        reinterpret_cast<float4*>(Cb)[t] = o;
    }
}

extern "C" void kernel_launch(void* const* d_in, const int* in_sizes, int n_in,
                              void* d_out, int out_size) {
    const float* Q = (const float*)d_in[0];
    const float* K = (const float*)d_in[1];
    const float* V = (const float*)d_in[2];
    const float* M = (const float*)d_in[3];

    float* ctx  = (float*)d_out;
    float* attn = (float*)d_out + (size_t)Bc * Hc * Sc * Dc;  // context first, then attention

    const size_t smem_bytes = (size_t)SM_FLOATS * sizeof(float);
    cudaFuncSetAttribute(attn_fused_kernel,
                         cudaFuncAttributeMaxDynamicSharedMemorySize,
                         (int)smem_bytes);

    dim3 grid(Sc / TQ, Bc * Hc);   // (128, 32)
    attn_fused_kernel<<<grid, NT, smem_bytes>>>(Q, K, V, M, ctx, attn);
}

// round 2
// speedup vs baseline: 1.0696x; 1.0696x over previous
#include <cuda_runtime.h>

// ============================================================================
// Fused scaled-dot-product attention (fp32), B=2 H=16 S=2048 D=64.
// Outputs: d_out[0 : B*H*S*D)          = context
//          d_out[B*H*S*D : +B*H*S*S)   = attention (post-softmax)
//
// One block = one (b*h, 16-query-row) tile. Crossbar-balanced SIMT design:
//  - Phase 1 (QK^T): thread computes 8 q-rows x 2 k-cols; Q operands arrive
//    as .128 broadcast register pairs (zero-MOV f32x2 packing), K re-read
//    from smem only 2x.
//  - Softmax: unnormalized exp kept in smem; 1/sum folded into the gmem
//    attention store and into the context accumulators (one fewer SC pass).
//  - Phase 2 (P@V): warp-per-k-slice, thread computes 8 q-rows x 4 d-cols,
//    V re-read only 2x, partial k-sums reduced through smem.
// ============================================================================

namespace {

constexpr int Bc  = 2;
constexpr int Hc  = 16;
constexpr int Sc  = 2048;
constexpr int Dc  = 64;
constexpr int TQ  = 16;    // query rows per block
constexpr int KTW = 256;   // K-tile width (score columns per supertile)
constexpr int KP  = 65;    // K smem pitch (odd -> conflict-free column reads)
constexpr int SP  = 2052;  // score row pitch
constexpr int NT  = 256;   // threads per block

constexpr int SM_QT     = 0;                   // Qt[d][q]  : 64*16 = 1024
constexpr int SM_INV    = SM_QT + Dc * TQ;     // inv[16]
constexpr int SM_SC     = SM_INV + 16;         // SC[q][SP] : 16*2052
constexpr int SM_KV     = SM_SC + TQ * SP;     // KV: K tile 256*65 / V tile / partials
constexpr int SM_FLOATS = SM_KV + KTW * KP;    // 50512 floats = 202048 bytes

__device__ __forceinline__ unsigned long long pk2(float x, float y) {
    unsigned long long r;
    asm("mov.b64 %0, {%1, %2};"
        : "=l"(r) : "r"(__float_as_uint(x)), "r"(__float_as_uint(y)));
    return r;
}

__device__ __forceinline__ void upk2(unsigned long long v, float& x, float& y) {
    unsigned int a, b;
    asm("mov.b64 {%0, %1}, %2;" : "=r"(a), "=r"(b) : "l"(v));
    x = __uint_as_float(a);
    y = __uint_as_float(b);
}

__device__ __forceinline__ unsigned long long
fma2(unsigned long long a, unsigned long long b, unsigned long long c) {
    unsigned long long d;
    asm("fma.rn.f32x2 %0, %1, %2, %3;" : "=l"(d) : "l"(a), "l"(b), "l"(c));
    return d;
}

} // namespace

__global__ void __launch_bounds__(NT, 1)
attn_fused_kernel(const float* __restrict__ Q, const float* __restrict__ K,
                  const float* __restrict__ V, const float* __restrict__ M,
                  float* __restrict__ OC, float* __restrict__ OA)
{
    extern __shared__ float sm[];
    float* Qt    = sm + SM_QT;
    float* sminv = sm + SM_INV;
    float* SC    = sm + SM_SC;
    float* KV    = sm + SM_KV;

    const int t  = threadIdx.x;
    const int qt = blockIdx.x;   // query tile (0..127)
    const int bh = blockIdx.y;   // b*H + h    (0..31)

    const float* Qb = Q + ((long)bh * Sc + qt * TQ) * Dc;
    const float* Kb = K + (long)bh * Sc * Dc;
    const float* Vb = V + (long)bh * Sc * Dc;
    const float* Mb = M + ((long)bh * Sc + (long)qt * TQ) * Sc;
    float*       Ab = OA + ((long)bh * Sc + (long)qt * TQ) * Sc;
    float*       Cb = OC + ((long)bh * Sc + qt * TQ) * Dc;

    // ---------------- Phase 0: stage Q transposed (Qt[d][q]) ----------------
    {
        const int q  = t >> 4;          // 0..15
        const int d0 = (t & 15) << 2;   // 0,4,...,60
        float4 v = *reinterpret_cast<const float4*>(Qb + q * Dc + d0);
        Qt[(d0 + 0) * TQ + q] = v.x;
        Qt[(d0 + 1) * TQ + q] = v.y;
        Qt[(d0 + 2) * TQ + q] = v.z;
        Qt[(d0 + 3) * TQ + q] = v.w;
    }

    const int a = t >> 7;    // q octet: rows 8a..8a+7
    const int g = t & 127;   // k lane : columns g, g+128

    // ---------------- Phase 1: S = exp-arg = (Q K^T) * 1/sqrt(D) ------------
    const float scl = 0.125f;  // 1/sqrt(64)
    for (int st = 0; st < Sc / KTW; ++st) {
        __syncthreads();
        // Load K supertile rows [st*256, +256) into KV[k][KP], coalesced LDG.
        {
            const float* src = Kb + (long)st * KTW * Dc;
            #pragma unroll
            for (int ii = 0; ii < (KTW * Dc) / (NT * 4); ++ii) {  // 16 iters
                const int idx4 = t + NT * ii;
                const int kr = idx4 >> 4;
                const int d0 = (idx4 & 15) << 2;
                float4 v = *reinterpret_cast<const float4*>(src + (size_t)idx4 * 4);
                float* dst = KV + kr * KP + d0;
                dst[0] = v.x; dst[1] = v.y; dst[2] = v.z; dst[3] = v.w;
            }
        }
        __syncthreads();

        // acc[j][c]: q-pair j (rows 8a+2j, 8a+2j+1), column c (g / g+128)
        unsigned long long a00 = 0ull, a01 = 0ull, a10 = 0ull, a11 = 0ull,
                           a20 = 0ull, a21 = 0ull, a30 = 0ull, a31 = 0ull;
        #pragma unroll 8
        for (int d = 0; d < Dc; ++d) {
            // Q pairs as register pairs straight from .128 broadcast loads.
            const ulonglong2 qA =
                *reinterpret_cast<const ulonglong2*>(Qt + d * TQ + 8 * a);
            const ulonglong2 qB =
                *reinterpret_cast<const ulonglong2*>(Qt + d * TQ + 8 * a + 4);
            const float k0 = KV[(g      ) * KP + d];
            const float k1 = KV[(g + 128) * KP + d];
            const unsigned long long kk0 = pk2(k0, k0);
            const unsigned long long kk1 = pk2(k1, k1);
            a00 = fma2(qA.x, kk0, a00);  a01 = fma2(qA.x, kk1, a01);
            a10 = fma2(qA.y, kk0, a10);  a11 = fma2(qA.y, kk1, a11);
            a20 = fma2(qB.x, kk0, a20);  a21 = fma2(qB.x, kk1, a21);
            a30 = fma2(qB.y, kk0, a30);  a31 = fma2(qB.y, kk1, a31);
        }

        {
            float s0, s1;
            float* col = SC + st * KTW + g;
            upk2(a00, s0, s1);
            col[(8*a + 0) * SP] = s0 * scl;  col[(8*a + 1) * SP] = s1 * scl;
            upk2(a10, s0, s1);
            col[(8*a + 2) * SP] = s0 * scl;  col[(8*a + 3) * SP] = s1 * scl;
            upk2(a20, s0, s1);
            col[(8*a + 4) * SP] = s0 * scl;  col[(8*a + 5) * SP] = s1 * scl;
            upk2(a30, s0, s1);
            col[(8*a + 6) * SP] = s0 * scl;  col[(8*a + 7) * SP] = s1 * scl;

            float* col2 = col + 128;
            upk2(a01, s0, s1);
            col2[(8*a + 0) * SP] = s0 * scl;  col2[(8*a + 1) * SP] = s1 * scl;
            upk2(a11, s0, s1);
            col2[(8*a + 2) * SP] = s0 * scl;  col2[(8*a + 3) * SP] = s1 * scl;
            upk2(a21, s0, s1);
            col2[(8*a + 4) * SP] = s0 * scl;  col2[(8*a + 5) * SP] = s1 * scl;
            upk2(a31, s0, s1);
            col2[(8*a + 6) * SP] = s0 * scl;  col2[(8*a + 7) * SP] = s1 * scl;
        }
    }
    __syncthreads();

    // ------- Softmax (+mask): leave UNNORMALIZED exp in SC; write attention -
    {
        const int w = t >> 5, lane = t & 31;
        #pragma unroll
        for (int rr = 0; rr < 2; ++rr) {
            const int r = w * 2 + rr;           // 8 warps x 2 rows = 16 rows
            float* row = SC + r * SP;
            const float* mrow = Mb + (long)r * Sc;

            float mx = -3.0e38f;
            #pragma unroll
            for (int i = 0; i < Sc / 128; ++i) {  // 16 iters of float4
                const int c = (lane + i * 32) << 2;
                float4 s = *reinterpret_cast<float4*>(row + c);
                const float4 m = *reinterpret_cast<const float4*>(mrow + c);
                s.x += m.x; s.y += m.y; s.z += m.z; s.w += m.w;
                *reinterpret_cast<float4*>(row + c) = s;
                mx = fmaxf(mx, fmaxf(fmaxf(s.x, s.y), fmaxf(s.z, s.w)));
            }
            #pragma unroll
            for (int o = 16; o > 0; o >>= 1)
                mx = fmaxf(mx, __shfl_xor_sync(0xffffffffu, mx, o));

            float sum = 0.f;
            #pragma unroll
            for (int i = 0; i < Sc / 128; ++i) {
                const int c = (lane + i * 32) << 2;
                float4 s = *reinterpret_cast<float4*>(row + c);
                s.x = __expf(s.x - mx); s.y = __expf(s.y - mx);
                s.z = __expf(s.z - mx); s.w = __expf(s.w - mx);
                *reinterpret_cast<float4*>(row + c) = s;   // unnormalized exp
                sum += (s.x + s.y) + (s.z + s.w);
            }
            #pragma unroll
            for (int o = 16; o > 0; o >>= 1)
                sum += __shfl_xor_sync(0xffffffffu, sum, o);
            const float inv = 1.0f / sum;
            if (lane == 0) sminv[r] = inv;

            float* arow = Ab + (long)r * Sc;
            #pragma unroll
            for (int i = 0; i < Sc / 128; ++i) {
                const int c = (lane + i * 32) << 2;
                float4 s = *reinterpret_cast<float4*>(row + c);
                s.x *= inv; s.y *= inv; s.z *= inv; s.w *= inv;
                *reinterpret_cast<float4*>(arow + c) = s;  // attention out only
            }
        }
    }

    // ---------------- Phase 2: C = P @ V (P = unnormalized exp) -------------
    const int p  = t >> 5;         // warp id: k rows p*16..p*16+15 per V tile
    const int a2 = (t >> 4) & 1;   // q octet: rows 8*a2..8*a2+7
    const int dg = t & 15;         // d quad : cols 4*dg..4*dg+3

    unsigned long long cA[8], cB[8];   // per q-row r: (d0,d1) and (d2,d3)
    #pragma unroll
    for (int r = 0; r < 8; ++r) { cA[r] = 0ull; cB[r] = 0ull; }

    for (int vt = 0; vt < Sc / 128; ++vt) {   // 16 V tiles of 128 rows
        __syncthreads();
        {
            const float4* src =
                reinterpret_cast<const float4*>(Vb + (long)vt * 128 * Dc);
            float4* dst = reinterpret_cast<float4*>(KV);
            #pragma unroll
            for (int ii = 0; ii < (128 * Dc) / (NT * 4); ++ii)  // 8 iters
                dst[t + NT * ii] = src[t + NT * ii];
        }
        __syncthreads();

        const float* pcb = SC + vt * 128 + p * 16;
        #pragma unroll
        for (int kk = 0; kk < 16; kk += 2) {
            const float* vrow = KV + (p * 16 + kk) * Dc + 4 * dg;
            const ulonglong2 v0 = *reinterpret_cast<const ulonglong2*>(vrow);
            const ulonglong2 v1 = *reinterpret_cast<const ulonglong2*>(vrow + Dc);
            #pragma unroll
            for (int r = 0; r < 8; ++r) {
                const float2 pv =
                    *reinterpret_cast<const float2*>(pcb + (8*a2 + r) * SP + kk);
                const unsigned long long pa = pk2(pv.x, pv.x);
                const unsigned long long pb = pk2(pv.y, pv.y);
                cA[r] = fma2(pa, v0.x, cA[r]);
                cB[r] = fma2(pa, v0.y, cB[r]);
                cA[r] = fma2(pb, v1.x, cA[r]);
                cB[r] = fma2(pb, v1.y, cB[r]);
            }
        }
    }

    // Scale partials by 1/sum, store per-warp partials, reduce over 8 slices.
    __syncthreads();
    #pragma unroll
    for (int r = 0; r < 8; ++r) {
        const int row = 8 * a2 + r;
        const float inv = sminv[row];
        float s0, s1, s2, s3;
        upk2(cA[r], s0, s1);
        upk2(cB[r], s2, s3);
        *reinterpret_cast<float4*>(KV + p * 1024 + row * Dc + 4 * dg) =
            make_float4(s0 * inv, s1 * inv, s2 * inv, s3 * inv);
    }
    __syncthreads();
    {
        const float4* kv4 = reinterpret_cast<const float4*>(KV);
        float4 o = make_float4(0.f, 0.f, 0.f, 0.f);
        #pragma unroll
        for (int pp = 0; pp < 8; ++pp) {
            const float4 r = kv4[pp * 256 + t];
            o.x += r.x; o.y += r.y; o.z += r.z; o.w += r.w;
        }
        reinterpret_cast<float4*>(Cb)[t] = o;
    }
}

extern "C" void kernel_launch(void* const* d_in, const int* in_sizes, int n_in,
                              void* d_out, int out_size) {
    const float* Q = (const float*)d_in[0];
    const float* K = (const float*)d_in[1];
    const float* V = (const float*)d_in[2];
    const float* M = (const float*)d_in[3];

    float* ctx  = (float*)d_out;
    float* attn = (float*)d_out + (size_t)Bc * Hc * Sc * Dc;  // context, then attention

    const size_t smem_bytes = (size_t)SM_FLOATS * sizeof(float);
    cudaFuncSetAttribute(attn_fused_kernel,
                         cudaFuncAttributeMaxDynamicSharedMemorySize,
                         (int)smem_bytes);

    dim3 grid(Sc / TQ, Bc * Hc);   // (128, 32)
    attn_fused_kernel<<<grid, NT, smem_bytes>>>(Q, K, V, M, ctx, attn);
}